// round 4
// baseline (speedup 1.0000x reference)
#include <cuda_runtime.h>

// Problem constants (fixed shapes for this problem instance)
#define NBOX   2048
#define NBATCH 16
#define AH     256
#define AW     256
#define GRID   256   // NBATCH * 16 row-groups

__device__ float        g_partial[GRID];
__device__ unsigned int g_count = 0;

__device__ __forceinline__ float bce_elem(float l, unsigned mb) {
    // max(l,0) - l*m + log1p(exp(-|l|))
    float m = mb ? 1.0f : 0.0f;
    return fmaxf(l, 0.0f) - l * m + log1pf(__expf(-fabsf(l)));
}

__global__ __launch_bounds__(256, 4)
void la_loss_kernel(const float* __restrict__ am,
                    const float* __restrict__ tgt,
                    float* __restrict__ out)
{
    const int tid   = threadIdx.x;
    const int blk   = blockIdx.x;
    const int batch = blk >> 4;   // 0..15
    const int rg    = blk & 15;   // row group: rows [rg*16, rg*16+16)

    __shared__ ushort4  s_rect[NBOX];        // 16 KB worst case (all boxes one batch)
    __shared__ unsigned s_rowmask[16 * 8];   // 16 rows x 256 bits
    __shared__ float    s_warp[8];
    __shared__ int      s_s, s_e;
    __shared__ unsigned s_last;

    if (tid == 0) { s_s = NBOX; s_e = NBOX; }
    if (tid < 128) s_rowmask[tid] = 0u;
    __syncthreads();

    // ---- Phase 0: find box range [s,e) for this batch (bidx is sorted) ----
    {
        int ls = NBOX, le = NBOX;
        const float fb  = (float)batch;
        const float fb1 = (float)(batch + 1);
        for (int k = tid; k < NBOX; k += 256) {
            float bv = tgt[k * 6];
            if (bv >= fb  && k < ls) ls = k;
            if (bv >= fb1 && k < le) le = k;
        }
        atomicMin(&s_s, ls);
        atomicMin(&s_e, le);
    }
    __syncthreads();
    const int s   = s_s;
    const int e   = s_e;
    const int cnt = e - s;

    // ---- Phase 1: precompute clipped integer rects into shared ----
    for (int i = tid; i < cnt; i += 256) {
        const float* t = tgt + (size_t)(s + i) * 6;
        float xc = t[2], yc = t[3], bw = t[4], bh = t[5];
        float x1 = 1024.0f * (xc - bw * 0.5f);
        float y1 = 1024.0f * (yc - bh * 0.5f);
        float x2 = 1024.0f * (xc + bw * 0.5f);
        float y2 = 1024.0f * (yc + bh * 0.5f);
        bool valid = (x1 <= 1024.0f) && (y1 <= 1024.0f) &&
                     (x2 <= 1024.0f) && (y2 <= 1024.0f);
        int X1 = max(0, (int)truncf(x1 * 0.25f));
        int Y1 = max(0, (int)truncf(y1 * 0.25f));
        int X2 = max(0, min(AW, (int)(ceilf(x2 * 0.25f) + 1.0f)));
        int Y2 = max(0, min(AH, (int)(ceilf(y2 * 0.25f) + 1.0f)));
        if (!valid) { X1 = X2 = Y1 = Y2 = 0; }
        s_rect[i] = make_ushort4((unsigned short)X1, (unsigned short)X2,
                                 (unsigned short)Y1, (unsigned short)Y2);
    }
    __syncthreads();

    // ---- Phase 2: rasterize union bitmask for this block's 16 rows ----
    // layout: ty = tid>>4 selects the row, lane16 = tid&15 strides over boxes
    {
        const int ty     = tid >> 4;
        const int lane16 = tid & 15;
        const int y      = rg * 16 + ty;
        unsigned m[8] = {0, 0, 0, 0, 0, 0, 0, 0};
        for (int i = lane16; i < cnt; i += 16) {
            ushort4 r = s_rect[i];
            if (y >= (int)r.z && y < (int)r.w) {
                int X1 = (int)r.x, X2 = (int)r.y;
                #pragma unroll
                for (int w = 0; w < 8; w++) {
                    int lo = min(max(X1 - w * 32, 0), 32);
                    int hi = min(max(X2 - w * 32, 0), 32);
                    unsigned mh = (hi >= 32) ? 0xFFFFFFFFu : ((1u << hi) - 1u);
                    unsigned ml = (lo >= 32) ? 0xFFFFFFFFu : ((1u << lo) - 1u);
                    m[w] |= mh & ~ml;   // zero when lo >= hi
                }
            }
        }
        #pragma unroll
        for (int w = 0; w < 8; w++)
            if (m[w]) atomicOr(&s_rowmask[ty * 8 + w], m[w]);
    }
    __syncthreads();

    // ---- Phase 3: BCE over this block's contiguous 4096 logits (float4) ----
    float sum = 0.0f;
    {
        const float4* am4  = (const float4*)am;
        const size_t base4 = (size_t)blk * 1024;   // 4096 floats per block
        #pragma unroll
        for (int j = 0; j < 4; j++) {
            int p = tid + j * 256;                 // float4 index within chunk
            float4 v = am4[base4 + p];
            int ty  = p >> 6;                      // 64 float4 per row
            int col = (p & 63) << 2;               // starting bit (multiple of 4)
            unsigned bits = s_rowmask[ty * 8 + (col >> 5)] >> (col & 31);
            sum += bce_elem(v.x,  bits       & 1u);
            sum += bce_elem(v.y, (bits >> 1) & 1u);
            sum += bce_elem(v.z, (bits >> 2) & 1u);
            sum += bce_elem(v.w, (bits >> 3) & 1u);
        }
    }

    // ---- Phase 4: block reduce (deterministic), scale, publish partial ----
    {
        #pragma unroll
        for (int off = 16; off; off >>= 1)
            sum += __shfl_down_sync(0xFFFFFFFFu, sum, off);
        if ((tid & 31) == 0) s_warp[tid >> 5] = sum;
    }
    __syncthreads();
    if (tid == 0) {
        float tot = 0.0f;
        #pragma unroll
        for (int w = 0; w < 8; w++) tot += s_warp[w];   // fixed order
        float partial = (cnt > 0) ? tot * (1.0f / 65536.0f) : 0.0f;
        g_partial[blk] = partial;
        __threadfence();
        unsigned prev = atomicAdd(&g_count, 1u);
        s_last = (prev == (unsigned)(gridDim.x - 1)) ? 1u : 0u;
    }
    __syncthreads();

    // ---- Phase 5: last block sums all partials in a FIXED order (deterministic) ----
    if (s_last && tid < 32) {
        __threadfence();
        float v = 0.0f;
        for (int i = tid; i < GRID; i += 32)
            v += *((volatile float*)&g_partial[i]);
        #pragma unroll
        for (int off = 16; off; off >>= 1)
            v += __shfl_down_sync(0xFFFFFFFFu, v, off);
        if (tid == 0) {
            out[0]  = v;
            g_count = 0u;   // reset for next graph replay
        }
    }
}

extern "C" void kernel_launch(void* const* d_in, const int* in_sizes, int n_in,
                              void* d_out, int out_size)
{
    const float* am  = (const float*)d_in[0];  // attention_mask (16,1,256,256) f32
    const float* tgt = (const float*)d_in[1];  // target (2048,6) f32
    (void)in_sizes; (void)n_in; (void)out_size;
    la_loss_kernel<<<GRID, 256>>>(am, tgt, (float*)d_out);
}

// round 5
// speedup vs baseline: 1.0717x; 1.0717x over previous
#include <cuda_runtime.h>

// Problem constants (fixed shapes for this problem instance)
#define NBOX   2048
#define NBATCH 16
#define AH     256
#define AW     256
#define GRID   256   // NBATCH * 16 row-groups

__device__ float        g_partial[GRID];
__device__ unsigned int g_count = 0;

// bce = max(l,0) - l*m + log1p(exp(-|l|))
// softplus term via raw MUFU: ln2 * lg2(1 + ex2(-|l|*log2e)).
// Arg of lg2 is in (1,2] for every l -> no overflow, abs err ~3e-7.
__device__ __forceinline__ float bce_elem(float l, unsigned mb) {
    float t  = __expf(-fabsf(l));          // FMA + MUFU.EX2
    float sp = __logf(1.0f + t);           // ADD + MUFU.LG2 + MUL
    float z  = fmaxf(l, 0.0f) - (mb ? l : 0.0f);
    return z + sp;
}

__global__ __launch_bounds__(256, 4)
void la_loss_kernel(const float* __restrict__ am,
                    const float* __restrict__ tgt,
                    float* __restrict__ out)
{
    const int tid   = threadIdx.x;
    const int blk   = blockIdx.x;
    const int batch = blk >> 4;   // 0..15
    const int rg    = blk & 15;   // row group: rows [rg*16, rg*16+16)

    // ---- Prefetch this block's 4096 logits NOW; consumed in Phase 3.
    // DRAM latency (~577cyc) hides under phases 0-2.
    const float4* am4  = (const float4*)am;
    const size_t base4 = (size_t)blk * 1024;
    float4 v0 = am4[base4 + tid];
    float4 v1 = am4[base4 + tid + 256];
    float4 v2 = am4[base4 + tid + 512];
    float4 v3 = am4[base4 + tid + 768];

    __shared__ ushort4  s_rect[NBOX];        // 16 KB worst case
    __shared__ unsigned s_rowmask[16 * 8];   // 16 rows x 256 bits
    __shared__ float    s_warp[8];
    __shared__ int      s_c0, s_c1;
    __shared__ unsigned s_last;

    if (tid == 0) { s_c0 = 0; s_c1 = 0; }
    if (tid < 128) s_rowmask[tid] = 0u;
    __syncthreads();

    // ---- Phase 0: box range [s,e) for this batch via sorted prefix counts ----
    {
        const float fb  = (float)batch;
        const float fb1 = (float)(batch + 1);
        int c0 = 0, c1 = 0;
        #pragma unroll
        for (int k = 0; k < NBOX / 256; k++) {
            float bv = tgt[(tid + k * 256) * 6];
            c0 += (bv < fb)  ? 1 : 0;
            c1 += (bv < fb1) ? 1 : 0;
        }
        c0 = __reduce_add_sync(0xFFFFFFFFu, c0);
        c1 = __reduce_add_sync(0xFFFFFFFFu, c1);
        if ((tid & 31) == 0) {
            atomicAdd(&s_c0, c0);
            atomicAdd(&s_c1, c1);
        }
    }
    __syncthreads();
    const int s   = s_c0;
    const int e   = s_c1;
    const int cnt = e - s;

    // ---- Phase 1: precompute clipped integer rects into shared ----
    for (int i = tid; i < cnt; i += 256) {
        const float* t = tgt + (size_t)(s + i) * 6;
        float xc = t[2], yc = t[3], bw = t[4], bh = t[5];
        float x1 = 1024.0f * (xc - bw * 0.5f);
        float y1 = 1024.0f * (yc - bh * 0.5f);
        float x2 = 1024.0f * (xc + bw * 0.5f);
        float y2 = 1024.0f * (yc + bh * 0.5f);
        bool valid = (x1 <= 1024.0f) && (y1 <= 1024.0f) &&
                     (x2 <= 1024.0f) && (y2 <= 1024.0f);
        int X1 = max(0, (int)truncf(x1 * 0.25f));
        int Y1 = max(0, (int)truncf(y1 * 0.25f));
        int X2 = max(0, min(AW, (int)(ceilf(x2 * 0.25f) + 1.0f)));
        int Y2 = max(0, min(AH, (int)(ceilf(y2 * 0.25f) + 1.0f)));
        if (!valid) { X1 = X2 = Y1 = Y2 = 0; }
        s_rect[i] = make_ushort4((unsigned short)X1, (unsigned short)X2,
                                 (unsigned short)Y1, (unsigned short)Y2);
    }
    __syncthreads();

    // ---- Phase 2: rasterize union bitmask, touching only covered words ----
    // ty = tid>>4 selects the row, lane16 = tid&15 strides over boxes
    {
        const int ty     = tid >> 4;
        const int lane16 = tid & 15;
        const int y      = rg * 16 + ty;
        for (int i = lane16; i < cnt; i += 16) {
            ushort4 r = s_rect[i];
            if (y >= (int)r.z && y < (int)r.w && (int)r.y > (int)r.x) {
                int X1 = (int)r.x, X2 = (int)r.y;
                int w0 = X1 >> 5;
                int w1 = (X2 - 1) >> 5;
                for (int w = w0; w <= w1; w++) {
                    int lo = X1 - (w << 5); lo = (lo < 0) ? 0 : lo;   // 0..31
                    int hi = X2 - (w << 5);                            // >=1
                    unsigned mh  = (hi >= 32) ? 0xFFFFFFFFu : ((1u << hi) - 1u);
                    unsigned msk = mh & ~((1u << lo) - 1u);
                    atomicOr(&s_rowmask[(ty << 3) + w], msk);
                }
            }
        }
    }
    __syncthreads();

    // ---- Phase 3: BCE over prefetched logits ----
    float sum = 0.0f;
    {
        #pragma unroll
        for (int j = 0; j < 4; j++) {
            float4 v = (j == 0) ? v0 : (j == 1) ? v1 : (j == 2) ? v2 : v3;
            int p   = tid + j * 256;              // float4 index within chunk
            int ty  = p >> 6;                     // 64 float4 per row
            int col = (p & 63) << 2;              // starting bit (mult of 4)
            unsigned bits = s_rowmask[(ty << 3) + (col >> 5)] >> (col & 31);
            sum += bce_elem(v.x,  bits       & 1u);
            sum += bce_elem(v.y, (bits >> 1) & 1u);
            sum += bce_elem(v.z, (bits >> 2) & 1u);
            sum += bce_elem(v.w, (bits >> 3) & 1u);
        }
    }

    // ---- Phase 4: block reduce (deterministic order), publish partial ----
    {
        #pragma unroll
        for (int off = 16; off; off >>= 1)
            sum += __shfl_down_sync(0xFFFFFFFFu, sum, off);
        if ((tid & 31) == 0) s_warp[tid >> 5] = sum;
    }
    __syncthreads();
    if (tid == 0) {
        float tot = 0.0f;
        #pragma unroll
        for (int w = 0; w < 8; w++) tot += s_warp[w];   // fixed order
        float partial = (cnt > 0) ? tot * (1.0f / 65536.0f) : 0.0f;
        g_partial[blk] = partial;
        __threadfence();
        unsigned prev = atomicAdd(&g_count, 1u);
        s_last = (prev == (unsigned)(gridDim.x - 1)) ? 1u : 0u;
    }
    __syncthreads();

    // ---- Phase 5: last block sums partials in FIXED order (deterministic) ----
    if (s_last && tid < 32) {
        __threadfence();
        float v = 0.0f;
        for (int i = tid; i < GRID; i += 32)
            v += *((volatile float*)&g_partial[i]);
        #pragma unroll
        for (int off = 16; off; off >>= 1)
            v += __shfl_down_sync(0xFFFFFFFFu, v, off);
        if (tid == 0) {
            out[0]  = v;
            g_count = 0u;   // reset for next graph replay
        }
    }
}

extern "C" void kernel_launch(void* const* d_in, const int* in_sizes, int n_in,
                              void* d_out, int out_size)
{
    const float* am  = (const float*)d_in[0];  // attention_mask (16,1,256,256) f32
    const float* tgt = (const float*)d_in[1];  // target (2048,6) f32
    (void)in_sizes; (void)n_in; (void)out_size;
    la_loss_kernel<<<GRID, 256>>>(am, tgt, (float*)d_out);
}

// round 6
// speedup vs baseline: 1.4226x; 1.3274x over previous
#include <cuda_runtime.h>

// Problem constants (fixed shapes for this problem instance)
#define NBOX   2048
#define NBATCH 16
#define AH     256
#define AW     256
#define GRID   512   // NBATCH * 32 row-groups (8 rows per block)

__device__ float        g_partial[GRID];
__device__ unsigned int g_count = 0;

// bce = max(l,0) - l*m + log1p(exp(-|l|)); softplus arg in (1,2] -> safe fast math
__device__ __forceinline__ float bce_elem(float l, unsigned mb) {
    float t  = __expf(-fabsf(l));
    float sp = __logf(1.0f + t);
    float z  = fmaxf(l, 0.0f) - (mb ? l : 0.0f);
    return z + sp;
}

__global__ __launch_bounds__(256, 4)
void la_loss_kernel(const float* __restrict__ am,
                    const float* __restrict__ tgt,
                    float* __restrict__ out)
{
    const int tid   = threadIdx.x;
    const int blk   = blockIdx.x;
    const int batch = blk >> 5;   // 0..15
    const int rg    = blk & 31;   // row group: rows [rg*8, rg*8+8)

    // ---- Prefetch this block's 2048 logits (8 rows x 256) now; used in Phase 2.
    const float4* am4  = (const float4*)am;
    const size_t base4 = (size_t)blk * 512;      // 2048 floats per block
    float4 v0 = am4[base4 + tid];
    float4 v1 = am4[base4 + tid + 256];

    __shared__ ushort4  s_rect[NBOX];        // compacted non-empty rects (16 KB worst)
    __shared__ unsigned s_rowmask[8 * 8];    // 8 rows x 256 bits
    __shared__ float    s_warp[8];
    __shared__ int      s_nbox;              // boxes with bidx==batch (for has_box)
    __shared__ int      s_nrect;             // compacted rect count
    __shared__ unsigned s_last;

    if (tid == 0) { s_nbox = 0; s_nrect = 0; }
    if (tid < 64) s_rowmask[tid] = 0u;
    __syncthreads();

    // ---- Phase 1: single-pass scan + compaction of this batch's boxes ----
    // Order of compacted rects is irrelevant: the mask is a pure OR-union.
    {
        const float fb = (float)batch;
        #pragma unroll
        for (int k = 0; k < NBOX / 256; k++) {
            const int   i = tid + (k << 8);
            const float* t = tgt + (size_t)i * 6;
            float bv = t[0];
            if (bv == fb) {
                atomicAdd(&s_nbox, 1);
                float xc = t[2], yc = t[3], bw = t[4], bh = t[5];
                float x1 = 1024.0f * (xc - bw * 0.5f);
                float y1 = 1024.0f * (yc - bh * 0.5f);
                float x2 = 1024.0f * (xc + bw * 0.5f);
                float y2 = 1024.0f * (yc + bh * 0.5f);
                bool valid = (x1 <= 1024.0f) && (y1 <= 1024.0f) &&
                             (x2 <= 1024.0f) && (y2 <= 1024.0f);
                int X1 = max(0, (int)truncf(x1 * 0.25f));
                int Y1 = max(0, (int)truncf(y1 * 0.25f));
                int X2 = max(0, min(AW, (int)(ceilf(x2 * 0.25f) + 1.0f)));
                int Y2 = max(0, min(AH, (int)(ceilf(y2 * 0.25f) + 1.0f)));
                if (valid && X2 > X1 && Y2 > Y1) {
                    int slot = atomicAdd(&s_nrect, 1);
                    s_rect[slot] = make_ushort4((unsigned short)X1, (unsigned short)X2,
                                                (unsigned short)Y1, (unsigned short)Y2);
                }
            }
        }
    }
    __syncthreads();
    const int nrect = s_nrect;

    // ---- Phase 2a: rasterize union bitmask for this block's 8 rows ----
    // ty = tid>>5 selects row (8 rows), lane = tid&31 strides over rects
    {
        const int ty   = tid >> 5;
        const int lane = tid & 31;
        const int y    = (rg << 3) + ty;
        for (int i = lane; i < nrect; i += 32) {
            ushort4 r = s_rect[i];
            if (y >= (int)r.z && y < (int)r.w) {
                int X1 = (int)r.x, X2 = (int)r.y;
                int w0 = X1 >> 5;
                int w1 = (X2 - 1) >> 5;
                for (int w = w0; w <= w1; w++) {
                    int lo = X1 - (w << 5); lo = (lo < 0) ? 0 : lo;   // 0..31
                    int hi = X2 - (w << 5);                            // >=1
                    unsigned mh  = (hi >= 32) ? 0xFFFFFFFFu : ((1u << hi) - 1u);
                    unsigned msk = mh & ~((1u << lo) - 1u);
                    atomicOr(&s_rowmask[(ty << 3) + w], msk);
                }
            }
        }
    }
    __syncthreads();

    // ---- Phase 2b: BCE over prefetched logits (8 elems/thread) ----
    float sum = 0.0f;
    {
        #pragma unroll
        for (int j = 0; j < 2; j++) {
            float4 v = (j == 0) ? v0 : v1;
            int p   = tid + (j << 8);            // float4 index within chunk
            int ty  = p >> 6;                    // 64 float4 per row
            int col = (p & 63) << 2;             // starting bit (mult of 4)
            unsigned bits = s_rowmask[(ty << 3) + (col >> 5)] >> (col & 31);
            sum += bce_elem(v.x,  bits       & 1u);
            sum += bce_elem(v.y, (bits >> 1) & 1u);
            sum += bce_elem(v.z, (bits >> 2) & 1u);
            sum += bce_elem(v.w, (bits >> 3) & 1u);
        }
    }

    // ---- Phase 3: block reduce (fixed order), publish partial ----
    {
        #pragma unroll
        for (int off = 16; off; off >>= 1)
            sum += __shfl_down_sync(0xFFFFFFFFu, sum, off);
        if ((tid & 31) == 0) s_warp[tid >> 5] = sum;
    }
    __syncthreads();
    if (tid == 0) {
        float tot = 0.0f;
        #pragma unroll
        for (int w = 0; w < 8; w++) tot += s_warp[w];   // fixed order
        float partial = (s_nbox > 0) ? tot * (1.0f / 65536.0f) : 0.0f;
        g_partial[blk] = partial;
        __threadfence();
        unsigned prev = atomicAdd(&g_count, 1u);
        s_last = (prev == (unsigned)(gridDim.x - 1)) ? 1u : 0u;
    }
    __syncthreads();

    // ---- Phase 4: last block sums all partials, fixed order (deterministic) ----
    if (s_last) {
        __threadfence();
        float v = *((volatile float*)&g_partial[tid]) +
                  *((volatile float*)&g_partial[tid + 256]);
        #pragma unroll
        for (int off = 16; off; off >>= 1)
            v += __shfl_down_sync(0xFFFFFFFFu, v, off);
        if ((tid & 31) == 0) s_warp[tid >> 5] = v;
        __syncthreads();
        if (tid == 0) {
            float tot = 0.0f;
            #pragma unroll
            for (int w = 0; w < 8; w++) tot += s_warp[w];  // fixed order
            out[0]  = tot;
            g_count = 0u;   // reset for next graph replay
        }
    }
}

extern "C" void kernel_launch(void* const* d_in, const int* in_sizes, int n_in,
                              void* d_out, int out_size)
{
    const float* am  = (const float*)d_in[0];  // attention_mask (16,1,256,256) f32
    const float* tgt = (const float*)d_in[1];  // target (2048,6) f32
    (void)in_sizes; (void)n_in; (void)out_size;
    la_loss_kernel<<<GRID, 256>>>(am, tgt, (float*)d_out);
}